// round 5
// baseline (speedup 1.0000x reference)
#include <cuda_runtime.h>
#include <cstdint>

// ---------------- problem constants ----------------
static constexpr int S_TOK  = 2048;   // tokens (M)
static constexpr int K_DIM  = 4096;   // reduction dim
static constexpr int O_DIM  = 4096;   // outputs (N)
static constexpr int GROUPS = 32;     // K groups of 128

// GEMM tiling: int8 mma.sync m16n8k32 (base-arch). BK = 128 = one quant group
// per mainloop iteration, so the per-group fp32 rescale happens once per iter.
static constexpr int BM = 128;
static constexpr int BN = 128;
static constexpr int BK = 128;         // 128 int8 = 128 B rows
static constexpr int STAGES = 4;
static constexpr int NT = K_DIM / BK;  // 32 mainloop iterations
static constexpr int A_STAGE = BM * 128;   // 16 KB
static constexpr int B_STAGE = BN * 128;   // 16 KB
static constexpr int SC_STAGE = BN * 4;    // 512 B of per-group weight scales
static constexpr uint32_t SMEM_BYTES = STAGES * (A_STAGE + B_STAGE + SC_STAGE); // 130 KB

// ---------------- scratch (device globals; no allocs allowed) ----------------
__device__ __align__(1024) uint8_t g_Xq[(size_t)S_TOK * K_DIM];  // u8 activation codes (8 MB)
__device__ __align__(1024) int8_t  g_Ws8[(size_t)O_DIM * K_DIM]; // s8 centered weights (16 MB)
__device__ __align__(1024) float   g_wsT[GROUPS * O_DIM];        // ws transposed [g][n]
__device__ float g_corr[O_DIM];    // corr[n] = sum_g colsum[n,g]*ws[n,g]
__device__ float g_xs[S_TOK];      // per-token activation scale
__device__ float g_xz[S_TOK];      // per-token scale * zero_point

// ---------------- PTX helpers (base-arch only) ----------------
__device__ __forceinline__ uint32_t smem_u32(const void* p) {
    uint32_t a;
    asm("{ .reg .u64 t; cvta.to.shared.u64 t, %1; cvt.u32.u64 %0, t; }" : "=r"(a) : "l"(p));
    return a;
}
__device__ __forceinline__ void cp16(uint32_t dst, const void* src) {
    asm volatile("cp.async.cg.shared.global [%0], [%1], 16;" :: "r"(dst), "l"(src) : "memory");
}
__device__ __forceinline__ void ldm_x4(uint32_t* r, uint32_t a) {
    asm volatile("ldmatrix.sync.aligned.m8n8.x4.shared.b16 {%0,%1,%2,%3}, [%4];"
                 : "=r"(r[0]), "=r"(r[1]), "=r"(r[2]), "=r"(r[3]) : "r"(a));
}
// D = A*B + D  (in-place accumulate)
__device__ __forceinline__ void mma_u8s8_acc(int* d, const uint32_t* a, const uint32_t* b) {
    asm volatile(
        "mma.sync.aligned.m16n8k32.row.col.s32.u8.s8.s32 "
        "{%0,%1,%2,%3}, {%4,%5,%6,%7}, {%8,%9}, {%0,%1,%2,%3};"
        : "+r"(d[0]), "+r"(d[1]), "+r"(d[2]), "+r"(d[3])
        : "r"(a[0]), "r"(a[1]), "r"(a[2]), "r"(a[3]), "r"(b[0]), "r"(b[1]));
}
// D = A*B + 0  (fresh accumulator at group start; no explicit zeroing needed)
__device__ __forceinline__ void mma_u8s8_zro(int* d, const uint32_t* a, const uint32_t* b) {
    asm volatile(
        "mma.sync.aligned.m16n8k32.row.col.s32.u8.s8.s32 "
        "{%0,%1,%2,%3}, {%4,%5,%6,%7}, {%8,%9}, {%10,%10,%10,%10};"
        : "=r"(d[0]), "=r"(d[1]), "=r"(d[2]), "=r"(d[3])
        : "r"(a[0]), "r"(a[1]), "r"(a[2]), "r"(a[3]), "r"(b[0]), "r"(b[1]), "r"(0));
}

// ================= kernel 1: per-token activation quant =================
// q = clip(round(x/scale)+zp, 0,255) stored as u8; also xs, xs*zp per row.
__global__ void __launch_bounds__(256) act_quant_kernel(const float* __restrict__ x)
{
    const int row = blockIdx.x;
    const int t = threadIdx.x;
    const float4* xr = reinterpret_cast<const float4*>(x + (size_t)row * K_DIM);
    float4 v[4];
    float mn = 3.4e38f, mx = -3.4e38f;
#pragma unroll
    for (int i = 0; i < 4; i++) {
        v[i] = xr[t * 4 + i];
        mn = fminf(mn, fminf(fminf(v[i].x, v[i].y), fminf(v[i].z, v[i].w)));
        mx = fmaxf(mx, fmaxf(fmaxf(v[i].x, v[i].y), fmaxf(v[i].z, v[i].w)));
    }
#pragma unroll
    for (int o = 16; o > 0; o >>= 1) {
        mn = fminf(mn, __shfl_xor_sync(0xffffffffu, mn, o));
        mx = fmaxf(mx, __shfl_xor_sync(0xffffffffu, mx, o));
    }
    __shared__ float smn[8], smx[8];
    if ((t & 31) == 0) { smn[t >> 5] = mn; smx[t >> 5] = mx; }
    __syncthreads();
    mn = smn[0]; mx = smx[0];
#pragma unroll
    for (int i = 1; i < 8; i++) { mn = fminf(mn, smn[i]); mx = fmaxf(mx, smx[i]); }

    const float scale = fmaxf((mx - mn) / 255.0f, 1e-5f);
    const float zp = fminf(fmaxf(rintf(-mn / scale), 0.0f), 255.0f);

    float q[16];
    const float in[16] = {v[0].x, v[0].y, v[0].z, v[0].w, v[1].x, v[1].y, v[1].z, v[1].w,
                          v[2].x, v[2].y, v[2].z, v[2].w, v[3].x, v[3].y, v[3].z, v[3].w};
#pragma unroll
    for (int e = 0; e < 16; e++)
        q[e] = fminf(fmaxf(rintf(in[e] / scale) + zp, 0.0f), 255.0f);

    uint4 u;
    u.x = (unsigned)q[0]  | ((unsigned)q[1]  << 8) | ((unsigned)q[2]  << 16) | ((unsigned)q[3]  << 24);
    u.y = (unsigned)q[4]  | ((unsigned)q[5]  << 8) | ((unsigned)q[6]  << 16) | ((unsigned)q[7]  << 24);
    u.z = (unsigned)q[8]  | ((unsigned)q[9]  << 8) | ((unsigned)q[10] << 16) | ((unsigned)q[11] << 24);
    u.w = (unsigned)q[12] | ((unsigned)q[13] << 8) | ((unsigned)q[14] << 16) | ((unsigned)q[15] << 24);
    *reinterpret_cast<uint4*>(g_Xq + (size_t)row * K_DIM + t * 16) = u;

    if (t == 0) { g_xs[row] = scale; g_xz[row] = scale * zp; }
}

// ================= kernel 2: weight prep =================
// One block per output row n: write s8 centered codes, and corr[n] = sum_g colsum*ws.
__global__ void __launch_bounds__(256) w_prep_kernel(const int* __restrict__ qw,
                                                     const float* __restrict__ wsc,
                                                     const int* __restrict__ wzp)
{
    const int n = blockIdx.x;
    const int t = threadIdx.x;
    const int lane = t & 31;
    const int g = t >> 3;                 // 16 codes per thread -> group = t/8
    const int zp = __ldg(wzp + n * GROUPS + g);
    const float ws = __ldg(wsc + n * GROUPS + g);

    int codes[16];
    const int4* src = reinterpret_cast<const int4*>(qw + (size_t)n * K_DIM + t * 16);
#pragma unroll
    for (int i = 0; i < 4; i++) {
        int4 c4 = src[i];
        codes[i * 4 + 0] = c4.x; codes[i * 4 + 1] = c4.y;
        codes[i * 4 + 2] = c4.z; codes[i * 4 + 3] = c4.w;
    }
    int s16 = 0;
    uint32_t pk[4];
#pragma unroll
    for (int i = 0; i < 4; i++) {
        uint32_t p = 0;
#pragma unroll
        for (int j = 0; j < 4; j++) {
            const int c = codes[i * 4 + j];
            s16 += c;
            p |= (uint32_t)((c - zp) & 0xff) << (j * 8);
        }
        pk[i] = p;
    }
    uint4 w;
    w.x = pk[0]; w.y = pk[1]; w.z = pk[2]; w.w = pk[3];
    *reinterpret_cast<uint4*>(g_Ws8 + (size_t)n * K_DIM + t * 16) = w;

    // octet (8-thread) reduce -> per-group code sum
    int gs = s16;
#pragma unroll
    for (int o = 1; o < 8; o <<= 1) gs += __shfl_xor_sync(0xffffffffu, gs, o);
    // colsum contribution, leaders only, then warp-sum leaders
    float vcontrib = ((lane & 7) == 0) ? (float)(gs - 128 * zp) * ws : 0.0f;
    vcontrib += __shfl_xor_sync(0xffffffffu, vcontrib, 8);
    vcontrib += __shfl_xor_sync(0xffffffffu, vcontrib, 16);

    __shared__ float sw[8];
    if (lane == 0) sw[t >> 5] = vcontrib;
    __syncthreads();
    if (t == 0) {
        float acc = 0.0f;
#pragma unroll
        for (int i = 0; i < 8; i++) acc += sw[i];
        g_corr[n] = acc;
    }
}

// ================= kernel 3: transpose weight scales to [g][n] =================
__global__ void __launch_bounds__(256) wsT_kernel(const float* __restrict__ wsc)
{
    int idx = blockIdx.x * 256 + threadIdx.x;
    for (; idx < GROUPS * O_DIM; idx += gridDim.x * 256) {
        const int g = idx >> 12;          // / 4096
        const int n = idx & 4095;
        g_wsT[idx] = wsc[n * GROUPS + g];
    }
}

// ================= kernel 4: int8 multistage GEMM + grouped rescale =================
// acc_g[m,n] = sum_{k in g} q[m,k]*(w[n,k]-zw);  F = sum_g acc_g*ws[n,g]
// out = xs[m]*F - (xs[m]*zx[m])*corr[n] + bias[n]
// 256 threads = 8 warps, 4(m) x 2(n), warp tile 32 x 64.
__global__ void __launch_bounds__(256, 1) gemm_kernel(const float* __restrict__ bias,
                                                      float* __restrict__ out)
{
    extern __shared__ __align__(128) char smem[];
    const uint32_t sbA = smem_u32(smem);
    const uint32_t sbB = sbA + STAGES * A_STAGE;
    const uint32_t sbS = sbB + STAGES * B_STAGE;
    float* scS = reinterpret_cast<float*>(smem + STAGES * (A_STAGE + B_STAGE));

    const int tid = threadIdx.x;
    const int lane = tid & 31;
    const int wid = tid >> 5;
    const int wm = wid & 3;        // 4 warps along M (32 rows each)
    const int wn = wid >> 2;       // 2 warps along N (64 cols each)
    const int m0 = blockIdx.y * BM;
    const int n0 = blockIdx.x * BN;

    const int lrow = lane & 15;    // ldmatrix row within 16
    const int lcb  = lane >> 4;    // 16B k-chunk select

    float F[2][8][4];
#pragma unroll
    for (int mi = 0; mi < 2; mi++)
#pragma unroll
        for (int nf = 0; nf < 8; nf++)
#pragma unroll
            for (int e = 0; e < 4; e++) F[mi][nf][e] = 0.0f;

#define LOAD_STAGE(st, kt)                                                           \
    do {                                                                             \
        const uint8_t* gA = g_Xq + (size_t)m0 * K_DIM + (kt) * BK;                   \
        const int8_t*  gB = g_Ws8 + (size_t)n0 * K_DIM + (kt) * BK;                  \
        _Pragma("unroll")                                                            \
        for (int i = 0; i < 4; i++) {                                                \
            const int cid = tid + i * 256;                                           \
            const int row = cid >> 3;                                                \
            const int ch  = cid & 7;                                                 \
            const uint32_t off = (uint32_t)(row * 128 + ((ch ^ (row & 7)) << 4));    \
            cp16(sbA + (st) * A_STAGE + off, gA + (size_t)row * K_DIM + ch * 16);    \
            cp16(sbB + (st) * B_STAGE + off, gB + (size_t)row * K_DIM + ch * 16);    \
        }                                                                            \
        if (tid < 32)                                                                \
            cp16(sbS + (st) * SC_STAGE + tid * 16, g_wsT + (size_t)(kt) * O_DIM + n0 + tid * 4); \
    } while (0)

    LOAD_STAGE(0, 0);
    asm volatile("cp.async.commit_group;" ::: "memory");
    LOAD_STAGE(1, 1);
    asm volatile("cp.async.commit_group;" ::: "memory");
    LOAD_STAGE(2, 2);
    asm volatile("cp.async.commit_group;" ::: "memory");

    int st = 0;
    int stw = STAGES - 1;
    for (int kt = 0; kt < NT; kt++) {
        asm volatile("cp.async.wait_group 2;" ::: "memory");
        __syncthreads();

        const int nk = kt + STAGES - 1;
        if (nk < NT) { LOAD_STAGE(stw, nk); }
        asm volatile("cp.async.commit_group;" ::: "memory");
        stw = (stw == STAGES - 1) ? 0 : stw + 1;

        const uint32_t baseA = sbA + st * A_STAGE;
        const uint32_t baseB = sbB + st * B_STAGE;
        int acc[2][8][4];

#pragma unroll
        for (int ks = 0; ks < 4; ks++) {       // 4 x k32 = one 128-wide group
            uint32_t a[2][4];
#pragma unroll
            for (int mi = 0; mi < 2; mi++) {
                const int row = wm * 32 + mi * 16 + lrow;
                ldm_x4(a[mi], baseA + row * 128 + (((ks * 2 + lcb) ^ (row & 7)) << 4));
            }
#pragma unroll
            for (int nj = 0; nj < 4; nj++) {
                const int row = wn * 64 + nj * 16 + lrow;
                uint32_t r[4];
                ldm_x4(r, baseB + row * 128 + (((ks * 2 + lcb) ^ (row & 7)) << 4));
                uint32_t b0[2] = {r[0], r[2]};   // n 0-7 of this 16
                uint32_t b1[2] = {r[1], r[3]};   // n 8-15
#pragma unroll
                for (int mi = 0; mi < 2; mi++) {
                    if (ks == 0) {
                        mma_u8s8_zro(acc[mi][nj * 2 + 0], a[mi], b0);
                        mma_u8s8_zro(acc[mi][nj * 2 + 1], a[mi], b1);
                    } else {
                        mma_u8s8_acc(acc[mi][nj * 2 + 0], a[mi], b0);
                        mma_u8s8_acc(acc[mi][nj * 2 + 1], a[mi], b1);
                    }
                }
            }
        }

        // grouped rescale: F += (float)acc * ws[n, g=kt]
        const float* sg = scS + st * BN;
#pragma unroll
        for (int nf = 0; nf < 8; nf++) {
            const float2 wsv =
                *reinterpret_cast<const float2*>(sg + wn * 64 + nf * 8 + (lane & 3) * 2);
#pragma unroll
            for (int mi = 0; mi < 2; mi++) {
                F[mi][nf][0] += (float)acc[mi][nf][0] * wsv.x;
                F[mi][nf][1] += (float)acc[mi][nf][1] * wsv.y;
                F[mi][nf][2] += (float)acc[mi][nf][2] * wsv.x;
                F[mi][nf][3] += (float)acc[mi][nf][3] * wsv.y;
            }
        }
        st = (st == STAGES - 1) ? 0 : st + 1;
    }
#undef LOAD_STAGE

    // -------- epilogue: out = xs*F - (xs*zx)*corr + bias --------
    const int gm0 = m0 + wm * 32 + (lane >> 2);
    const int gn0 = n0 + wn * 64 + (lane & 3) * 2;
#pragma unroll
    for (int mi = 0; mi < 2; mi++) {
        const int r0 = gm0 + mi * 16;
        const float xs0 = g_xs[r0],     xz0 = g_xz[r0];
        const float xs1 = g_xs[r0 + 8], xz1 = g_xz[r0 + 8];
#pragma unroll
        for (int nf = 0; nf < 8; nf++) {
            const int col = gn0 + nf * 8;
            const float2 bi = *reinterpret_cast<const float2*>(bias + col);
            const float2 co = *reinterpret_cast<const float2*>(g_corr + col);
            float2 lo, hi;
            lo.x = fmaf(xs0, F[mi][nf][0], fmaf(-xz0, co.x, bi.x));
            lo.y = fmaf(xs0, F[mi][nf][1], fmaf(-xz0, co.y, bi.y));
            hi.x = fmaf(xs1, F[mi][nf][2], fmaf(-xz1, co.x, bi.x));
            hi.y = fmaf(xs1, F[mi][nf][3], fmaf(-xz1, co.y, bi.y));
            *reinterpret_cast<float2*>(out + (size_t)r0 * O_DIM + col) = lo;
            *reinterpret_cast<float2*>(out + (size_t)(r0 + 8) * O_DIM + col) = hi;
        }
    }
}

// ================= host launcher =================
extern "C" void kernel_launch(void* const* d_in, const int* in_sizes, int n_in,
                              void* d_out, int out_size)
{
    const float* x    = (const float*)d_in[0];
    const int*   qw   = (const int*)d_in[1];
    const float* wsc  = (const float*)d_in[2];
    const int*   wzp  = (const int*)d_in[3];
    const float* bias = (const float*)d_in[4];
    float* out = (float*)d_out;

    act_quant_kernel<<<S_TOK, 256>>>(x);
    w_prep_kernel<<<O_DIM, 256>>>(qw, wsc, wzp);
    wsT_kernel<<<128, 256>>>(wsc);

    cudaFuncSetAttribute(gemm_kernel, cudaFuncAttributeMaxDynamicSharedMemorySize,
                         SMEM_BYTES);
    gemm_kernel<<<dim3(O_DIM / BN, S_TOK / BM), 256, SMEM_BYTES>>>(bias, out);
}

// round 8
// speedup vs baseline: 2.4882x; 2.4882x over previous
#include <cuda_runtime.h>
#include <cuda_fp16.h>
#include <cstdint>

// ---------------- problem constants ----------------
static constexpr int S_TOK  = 2048;   // tokens (M)
static constexpr int K_DIM  = 4096;   // reduction dim
static constexpr int O_DIM  = 4096;   // outputs (N)
static constexpr int GROUPS = 32;     // K groups of 128

// GEMM tiling: fp16 mma.sync multistage (legacy HMMA — the only fast tensor
// path under the base-sm_103 compile target). BK=128 (two 128B panels per
// stage) halves the barrier count per tile vs BK=64.
static constexpr int BM = 128;
static constexpr int BN = 128;
static constexpr int BK = 128;         // 128 fp16 = 2 panels x 128 B rows
static constexpr int STAGES = 3;
static constexpr int NT = K_DIM / BK;  // 32 mainloop iterations
static constexpr int PANEL = 128 * 128;            // 16 KB (128 rows x 128 B)
static constexpr int A_STAGE = 2 * PANEL;          // 32 KB
static constexpr int B_STAGE = 2 * PANEL;          // 32 KB
static constexpr uint32_t SMEM_BYTES = STAGES * (A_STAGE + B_STAGE);  // 192 KB

// ---------------- scratch (device globals; no allocs allowed) ----------------
__device__ __align__(1024) __half g_Xc[(size_t)S_TOK * K_DIM];   // centered activations (fp16 exact ints)
__device__ __align__(1024) __half g_Wd[(size_t)O_DIM * K_DIM];   // dequantized weights (group scale folded)
__device__ float g_xs[S_TOK];                                    // per-token activation scale

// ---------------- PTX helpers (base-arch only) ----------------
__device__ __forceinline__ uint32_t smem_u32(const void* p) {
    uint32_t a;
    asm("{ .reg .u64 t; cvta.to.shared.u64 t, %1; cvt.u32.u64 %0, t; }" : "=r"(a) : "l"(p));
    return a;
}
__device__ __forceinline__ void cp16(uint32_t dst, const void* src) {
    asm volatile("cp.async.cg.shared.global [%0], [%1], 16;" :: "r"(dst), "l"(src) : "memory");
}
__device__ __forceinline__ void ldm_x4(uint32_t* r, uint32_t a) {
    asm volatile("ldmatrix.sync.aligned.m8n8.x4.shared.b16 {%0,%1,%2,%3}, [%4];"
                 : "=r"(r[0]), "=r"(r[1]), "=r"(r[2]), "=r"(r[3]) : "r"(a));
}
__device__ __forceinline__ void mma16816(float* d, const uint32_t* a, const uint32_t* b) {
    asm volatile(
        "mma.sync.aligned.m16n8k16.row.col.f32.f16.f16.f32 "
        "{%0,%1,%2,%3}, {%4,%5,%6,%7}, {%8,%9}, {%0,%1,%2,%3};"
        : "+f"(d[0]), "+f"(d[1]), "+f"(d[2]), "+f"(d[3])
        : "r"(a[0]), "r"(a[1]), "r"(a[2]), "r"(a[3]), "r"(b[0]), "r"(b[1]));
}

// ================= kernel 1: per-token activation quant =================
// centered = clip(rint(x/scale)+zp, 0,255) - zp; integers in [-255,255], exact in fp16
__global__ void __launch_bounds__(256) act_quant_kernel(const float* __restrict__ x)
{
    const int row = blockIdx.x;
    const int t = threadIdx.x;
    const float4* xr = reinterpret_cast<const float4*>(x + (size_t)row * K_DIM);
    float4 v[4];
    float mn = 3.4e38f, mx = -3.4e38f;
#pragma unroll
    for (int i = 0; i < 4; i++) {
        v[i] = xr[t * 4 + i];
        mn = fminf(mn, fminf(fminf(v[i].x, v[i].y), fminf(v[i].z, v[i].w)));
        mx = fmaxf(mx, fmaxf(fmaxf(v[i].x, v[i].y), fmaxf(v[i].z, v[i].w)));
    }
#pragma unroll
    for (int o = 16; o > 0; o >>= 1) {
        mn = fminf(mn, __shfl_xor_sync(0xffffffffu, mn, o));
        mx = fmaxf(mx, __shfl_xor_sync(0xffffffffu, mx, o));
    }
    __shared__ float smn[8], smx[8];
    if ((t & 31) == 0) { smn[t >> 5] = mn; smx[t >> 5] = mx; }
    __syncthreads();
    mn = smn[0]; mx = smx[0];
#pragma unroll
    for (int i = 1; i < 8; i++) { mn = fminf(mn, smn[i]); mx = fmaxf(mx, smx[i]); }

    const float scale = fmaxf((mx - mn) / 255.0f, 1e-5f);
    const float zp = fminf(fmaxf(rintf(-mn / scale), 0.0f), 255.0f);
    const float rs = 1.0f / scale;

    uint4* dst = reinterpret_cast<uint4*>(g_Xc + (size_t)row * K_DIM + t * 16);
#pragma unroll
    for (int h = 0; h < 2; h++) {
        const float4 a = v[2 * h], b = v[2 * h + 1];
        const float in[8] = {a.x, a.y, a.z, a.w, b.x, b.y, b.z, b.w};
        float c[8];
#pragma unroll
        for (int e = 0; e < 8; e++) {
            float q = fminf(fmaxf(rintf(in[e] * rs) + zp, 0.0f), 255.0f);
            c[e] = q - zp;
        }
        __half2 h0 = __floats2half2_rn(c[0], c[1]);
        __half2 h1 = __floats2half2_rn(c[2], c[3]);
        __half2 h2 = __floats2half2_rn(c[4], c[5]);
        __half2 h3 = __floats2half2_rn(c[6], c[7]);
        uint4 u;
        u.x = *reinterpret_cast<uint32_t*>(&h0);
        u.y = *reinterpret_cast<uint32_t*>(&h1);
        u.z = *reinterpret_cast<uint32_t*>(&h2);
        u.w = *reinterpret_cast<uint32_t*>(&h3);
        dst[h] = u;
    }
    if (t == 0) g_xs[row] = scale;
}

// ================= kernel 2: weight dequant (fold group scale into fp16) =================
__global__ void __launch_bounds__(256) w_dequant_kernel(const int* __restrict__ qw,
                                                        const float* __restrict__ wsc,
                                                        const int* __restrict__ wzp)
{
    const int idx = blockIdx.x * 256 + threadIdx.x;   // one thread = 4 K-elements
    const int o = idx >> 10;
    const int k = (idx & 1023) << 2;
    const int g = k >> 7;
    const int4 q = reinterpret_cast<const int4*>(qw)[((size_t)o * K_DIM + k) >> 2];
    const float s = __ldg(wsc + o * GROUPS + g);
    const float z = (float)__ldg(wzp + o * GROUPS + g);
    __half2 h0 = __floats2half2_rn(((float)q.x - z) * s, ((float)q.y - z) * s);
    __half2 h1 = __floats2half2_rn(((float)q.z - z) * s, ((float)q.w - z) * s);
    uint2 u;
    u.x = *reinterpret_cast<uint32_t*>(&h0);
    u.y = *reinterpret_cast<uint32_t*>(&h1);
    *reinterpret_cast<uint2*>(g_Wd + (size_t)o * K_DIM + k) = u;
}

// ================= kernel 3: multistage mma.sync GEMM + fused epilogue =================
// C[m,n] = sum_k Xc[m,k] * Wd[n,k];  out = C * xs[m] + bias[n]
// 256 threads = 8 warps in a 4(m) x 2(n) grid; warp tile 32 x 64.
// B ([N,K] row-major, K-contiguous) is col-major KxN for the mma -> non-trans ldmatrix.
// Stage layout: 2 K-panels per operand, each panel 128 rows x 128 B, XOR-swizzled.
__global__ void __launch_bounds__(256, 1) gemm_kernel(const float* __restrict__ bias,
                                                      float* __restrict__ out)
{
    extern __shared__ __align__(128) char smem[];
    const uint32_t sbA = smem_u32(smem);
    const uint32_t sbB = sbA + STAGES * A_STAGE;

    const int tid = threadIdx.x;
    const int lane = tid & 31;
    const int wid = tid >> 5;
    const int wm = wid & 3;        // 4 warps along M (32 rows each)
    const int wn = wid >> 2;       // 2 warps along N (64 cols each)
    const int m0 = blockIdx.y * BM;
    const int n0 = blockIdx.x * BN;

    // ldmatrix lane addressing: lanes 0-15 -> rows 0-15 (k 16B-chunk lcb=0 -> mats 0,1),
    // lanes 16-31 -> same rows at k-chunk lcb=1 (k+8 halves -> mats 2,3)
    const int lrow = lane & 15;
    const int lcb  = lane >> 4;

    float c[2][8][4];
#pragma unroll
    for (int mi = 0; mi < 2; mi++)
#pragma unroll
        for (int nf = 0; nf < 8; nf++)
#pragma unroll
            for (int e = 0; e < 4; e++) c[mi][nf][e] = 0.0f;

    // per stage per operand: 128 rows x 2 panels x 8 chunks = 2048 chunks; 8/thread.
    // cid -> row = cid>>4, panel = (cid>>3)&1, ch = cid&7
#define LOAD_STAGE(st, kt)                                                           \
    do {                                                                             \
        const __half* gA = g_Xc + (size_t)m0 * K_DIM + (size_t)(kt) * BK;            \
        const __half* gB = g_Wd + (size_t)n0 * K_DIM + (size_t)(kt) * BK;            \
        _Pragma("unroll")                                                            \
        for (int i = 0; i < 8; i++) {                                                \
            const int cid = tid + i * 256;                                           \
            const int row = cid >> 4;                                                \
            const int pan = (cid >> 3) & 1;                                          \
            const int ch  = cid & 7;                                                 \
            const uint32_t off =                                                     \
                (uint32_t)(pan * PANEL + row * 128 + ((ch ^ (row & 7)) << 4));       \
            const size_t gofs = (size_t)row * K_DIM + pan * 64 + ch * 8;             \
            cp16(sbA + (st) * A_STAGE + off, gA + gofs);                             \
            cp16(sbB + (st) * B_STAGE + off, gB + gofs);                             \
        }                                                                            \
    } while (0)

    // prologue: fill stages 0..STAGES-2
    LOAD_STAGE(0, 0);
    asm volatile("cp.async.commit_group;" ::: "memory");
    LOAD_STAGE(1, 1);
    asm volatile("cp.async.commit_group;" ::: "memory");

    int st = 0;        // compute stage
    int stw = 2;       // write stage
    for (int kt = 0; kt < NT; kt++) {
        asm volatile("cp.async.wait_group 1;" ::: "memory");
        __syncthreads();

        const int nk = kt + STAGES - 1;
        if (nk < NT) { LOAD_STAGE(stw, nk); }
        asm volatile("cp.async.commit_group;" ::: "memory");
        stw = (stw == STAGES - 1) ? 0 : stw + 1;

        const uint32_t baseA = sbA + st * A_STAGE;
        const uint32_t baseB = sbB + st * B_STAGE;
#pragma unroll
        for (int ks = 0; ks < 8; ks++) {       // 8 x k16 = BK 128
            const uint32_t pofs = (uint32_t)(ks >> 2) * PANEL;
            const int kk = ks & 3;
            uint32_t a[2][4];
            uint32_t b[8][2];
#pragma unroll
            for (int mi = 0; mi < 2; mi++) {
                const int row = wm * 32 + mi * 16 + lrow;
                const uint32_t ad =
                    baseA + pofs + row * 128 + (((kk * 2 + lcb) ^ (row & 7)) << 4);
                ldm_x4(a[mi], ad);
            }
#pragma unroll
            for (int nj = 0; nj < 4; nj++) {
                const int row = wn * 64 + nj * 16 + lrow;
                const uint32_t bd =
                    baseB + pofs + row * 128 + (((kk * 2 + lcb) ^ (row & 7)) << 4);
                uint32_t r[4];
                ldm_x4(r, bd);                 // non-trans: rows are n, cols are k
                b[nj * 2 + 0][0] = r[0];       // n 0-7,  k 0-7
                b[nj * 2 + 1][0] = r[1];       // n 8-15, k 0-7
                b[nj * 2 + 0][1] = r[2];       // n 0-7,  k 8-15
                b[nj * 2 + 1][1] = r[3];       // n 8-15, k 8-15
            }
#pragma unroll
            for (int mi = 0; mi < 2; mi++)
#pragma unroll
                for (int nf = 0; nf < 8; nf++)
                    mma16816(c[mi][nf], a[mi], b[nf]);
        }
        st = (st == STAGES - 1) ? 0 : st + 1;
    }
#undef LOAD_STAGE

    // -------- fused epilogue: out = acc * xs[m] + bias[n] --------
    const int gm0 = m0 + wm * 32 + (lane >> 2);
    const int gn0 = n0 + wn * 64 + (lane & 3) * 2;
#pragma unroll
    for (int mi = 0; mi < 2; mi++) {
        const int r0 = gm0 + mi * 16;
        const float xs0 = g_xs[r0];
        const float xs1 = g_xs[r0 + 8];
#pragma unroll
        for (int nf = 0; nf < 8; nf++) {
            const int col = gn0 + nf * 8;
            const float b0 = __ldg(bias + col);
            const float b1 = __ldg(bias + col + 1);
            float2 lo, hi;
            lo.x = c[mi][nf][0] * xs0 + b0;
            lo.y = c[mi][nf][1] * xs0 + b1;
            hi.x = c[mi][nf][2] * xs1 + b0;
            hi.y = c[mi][nf][3] * xs1 + b1;
            *reinterpret_cast<float2*>(out + (size_t)r0 * O_DIM + col) = lo;
            *reinterpret_cast<float2*>(out + (size_t)(r0 + 8) * O_DIM + col) = hi;
        }
    }
}

// ================= host launcher =================
extern "C" void kernel_launch(void* const* d_in, const int* in_sizes, int n_in,
                              void* d_out, int out_size)
{
    const float* x    = (const float*)d_in[0];
    const int*   qw   = (const int*)d_in[1];
    const float* wsc  = (const float*)d_in[2];
    const int*   wzp  = (const int*)d_in[3];
    const float* bias = (const float*)d_in[4];
    float* out = (float*)d_out;

    act_quant_kernel<<<S_TOK, 256>>>(x);
    w_dequant_kernel<<<(O_DIM * (K_DIM / 4)) / 256, 256>>>(qw, wsc, wzp);

    cudaFuncSetAttribute(gemm_kernel, cudaFuncAttributeMaxDynamicSharedMemorySize,
                         SMEM_BYTES);
    gemm_kernel<<<dim3(O_DIM / BN, S_TOK / BM), 256, SMEM_BYTES>>>(bias, out);
}